// round 2
// baseline (speedup 1.0000x reference)
#include <cuda_runtime.h>
#include <cstdint>

// Problem constants
#define DNODES 128
#define HID    512
#define NSAMP  2048

// Tiling
#define TN       64      // samples per block
#define NCHUNK   128     // N (output) chunk per pass
#define KT       32      // K rows per staged B tile
#define THREADS  256     // 8 warps: 4 (M) x 2 (N)

// SMEM strides (floats), padded for conflict-free access
#define LDX   132        // xs:  64 x 132
#define LDH   516        // h1:  64 x 516
#define LDB   136        // Bs:  KT x 136 (x2 buffers)

#define XS_OFF   0
#define H1_OFF   (XS_OFF + TN * LDX)                 // 8448
#define BS_OFF   (H1_OFF + TN * LDH)                 // 41472
#define BS_TILE  (KT * LDB)                          // 4352
#define W2_OFF   (BS_OFF + 2 * BS_TILE)              // 50176
#define OUT_OFF  (W2_OFF + HID)                      // 50688
#define SMEM_FLOATS (OUT_OFF + TN)                   // 50752
#define SMEM_BYTES (SMEM_FLOATS * 4)                 // 203008

__device__ __forceinline__ float to_tf32(float x) {
    float r;
    asm("cvt.rna.tf32.f32 %0, %1;" : "=f"(r) : "f"(x));
    return r;
}

__device__ __forceinline__ float leaky(float x) {
    return x > 0.0f ? x : 0.01f * x;
}

__device__ __forceinline__ void mma_tf32(float c[4],
                                         uint32_t a0, uint32_t a1, uint32_t a2, uint32_t a3,
                                         uint32_t b0, uint32_t b1) {
    asm volatile(
        "mma.sync.aligned.m16n8k8.row.col.f32.tf32.tf32.f32 "
        "{%0,%1,%2,%3},{%4,%5,%6,%7},{%8,%9},{%0,%1,%2,%3};"
        : "+f"(c[0]), "+f"(c[1]), "+f"(c[2]), "+f"(c[3])
        : "r"(a0), "r"(a1), "r"(a2), "r"(a3), "r"(b0), "r"(b1));
}

// Stage one KT x 128 fp32 tile: global -> registers
__device__ __forceinline__ void stage_ldg(const float* __restrict__ src, int ld,
                                          float4 regs[4], int tid) {
#pragma unroll
    for (int q = 0; q < 4; q++) {
        int fid = tid + q * THREADS;          // 0..1023 float4 ids
        int r = fid >> 5;                     // 32 float4 per row
        int c4 = fid & 31;
        regs[q] = *reinterpret_cast<const float4*>(src + (size_t)r * ld + c4 * 4);
    }
}

// registers -> smem tile (tf32-rounded)
__device__ __forceinline__ void stage_sts(float* __restrict__ bs, float4 regs[4], int tid) {
#pragma unroll
    for (int q = 0; q < 4; q++) {
        int fid = tid + q * THREADS;
        int r = fid >> 5;
        int c4 = fid & 31;
        float4 v = regs[q];
        v.x = to_tf32(v.x); v.y = to_tf32(v.y); v.z = to_tf32(v.z); v.w = to_tf32(v.w);
        *reinterpret_cast<float4*>(bs + r * LDB + c4 * 4) = v;
    }
}

// One staged B tile worth of MMAs: warp computes 16(M) x 64(N), K = KT
__device__ __forceinline__ void gemm_tile(const float* __restrict__ As, int lda,
                                          const float* __restrict__ Bs,
                                          float acc[8][4],
                                          int k0, int arow, int bcol, int g, int t4) {
#pragma unroll
    for (int kk = 0; kk < KT; kk += 8) {
        int ka = k0 + kk;
        uint32_t a0 = __float_as_uint(As[(arow + g)     * lda + ka + t4]);
        uint32_t a1 = __float_as_uint(As[(arow + g + 8) * lda + ka + t4]);
        uint32_t a2 = __float_as_uint(As[(arow + g)     * lda + ka + t4 + 4]);
        uint32_t a3 = __float_as_uint(As[(arow + g + 8) * lda + ka + t4 + 4]);
        const float* bp0 = Bs + (kk + t4)     * LDB + bcol + g;
        const float* bp1 = Bs + (kk + t4 + 4) * LDB + bcol + g;
#pragma unroll
        for (int s = 0; s < 8; s++) {
            mma_tf32(acc[s], a0, a1, a2, a3,
                     __float_as_uint(bp0[s * 8]), __float_as_uint(bp1[s * 8]));
        }
    }
}

extern __shared__ float smem[];

__global__ void __launch_bounds__(THREADS, 1)
grandag_fused_kernel(const float* __restrict__ x,
                     const float* __restrict__ W0,
                     const float* __restrict__ W1,
                     const float* __restrict__ W2,
                     float* __restrict__ out) {
    const int tid  = threadIdx.x;
    const int lane = tid & 31;
    const int warp = tid >> 5;
    const int wm = warp & 3;      // 0..3 (M)
    const int wn = warp >> 2;     // 0..1 (N)
    const int g  = lane >> 2;     // 0..7
    const int t4 = lane & 3;      // 0..3

    const int ntile = blockIdx.x;     // 0..31
    const int d     = blockIdx.y;     // 0..127
    const int n0    = ntile * TN;

    float* xs  = smem + XS_OFF;
    float* h1  = smem + H1_OFF;
    float* bs  = smem + BS_OFF;       // 2 buffers of BS_TILE
    float* w2s = smem + W2_OFF;
    float* outs = smem + OUT_OFF;

    // --- init: w2, outs, masked x tile (tf32-rounded) ---
    if (tid < TN) outs[tid] = 0.0f;
#pragma unroll
    for (int i = tid; i < HID; i += THREADS)
        w2s[i] = W2[(size_t)d * HID + i];

    for (int idx = tid; idx < TN * DNODES; idx += THREADS) {
        int m = idx >> 7;
        int i = idx & 127;
        float v = x[(size_t)(n0 + m) * DNODES + i];
        if (i == d) v = 0.0f;
        xs[m * LDX + i] = to_tf32(v);
    }

    const int arow = wm * 16;
    const int bcol = wn * 64;

    float p0 = 0.0f, p1 = 0.0f;   // fused layer-2 partials (rows arow+g, arow+g+8)
    float4 regs[4];
    float acc[8][4];

    // ================= Layer 0: K=128 (xs) -> h1 =================
    const float* w0base = W0 + (size_t)d * DNODES * HID;
#pragma unroll 1
    for (int nc = 0; nc < 4; nc++) {
#pragma unroll
        for (int s = 0; s < 8; s++)
#pragma unroll
            for (int j = 0; j < 4; j++) acc[s][j] = 0.0f;

        const float* wsrc = w0base + nc * NCHUNK;
        stage_ldg(wsrc, HID, regs, tid);
        __syncthreads();                      // Bs free (covers x/w2/outs init too)
        stage_sts(bs, regs, tid);

        const int T = DNODES / KT;            // 4
#pragma unroll 1
        for (int t = 0; t < T; t++) {
            __syncthreads();
            if (t + 1 < T) stage_ldg(wsrc + (size_t)(t + 1) * KT * HID, HID, regs, tid);
            gemm_tile(xs, LDX, bs + (t & 1) * BS_TILE, acc, t * KT, arow, bcol, g, t4);
            if (t + 1 < T) stage_sts(bs + ((t + 1) & 1) * BS_TILE, regs, tid);
        }

        // epilogue: leaky + tf32 -> h1
        int r0 = arow + g, r1 = r0 + 8;
#pragma unroll
        for (int s = 0; s < 8; s++) {
            int col = nc * NCHUNK + bcol + s * 8 + 2 * t4;
            float2 v0, v1;
            v0.x = to_tf32(leaky(acc[s][0]));
            v0.y = to_tf32(leaky(acc[s][1]));
            v1.x = to_tf32(leaky(acc[s][2]));
            v1.y = to_tf32(leaky(acc[s][3]));
            *reinterpret_cast<float2*>(h1 + r0 * LDH + col) = v0;
            *reinterpret_cast<float2*>(h1 + r1 * LDH + col) = v1;
        }
    }

    // ================= Layer 1: K=512 (h1), fused layer 2 =================
    const float* w1base = W1 + (size_t)d * HID * HID;
#pragma unroll 1
    for (int nc = 0; nc < 4; nc++) {
#pragma unroll
        for (int s = 0; s < 8; s++)
#pragma unroll
            for (int j = 0; j < 4; j++) acc[s][j] = 0.0f;

        const float* wsrc = w1base + nc * NCHUNK;
        stage_ldg(wsrc, HID, regs, tid);
        __syncthreads();                      // Bs free; also h1 complete before first gemm
        stage_sts(bs, regs, tid);

        const int T = HID / KT;               // 16
#pragma unroll 1
        for (int t = 0; t < T; t++) {
            __syncthreads();
            if (t + 1 < T) stage_ldg(wsrc + (size_t)(t + 1) * KT * HID, HID, regs, tid);
            gemm_tile(h1, LDH, bs + (t & 1) * BS_TILE, acc, t * KT, arow, bcol, g, t4);
            if (t + 1 < T) stage_sts(bs + ((t + 1) & 1) * BS_TILE, regs, tid);
        }

        // epilogue: leaky(h2) . W2 accumulated into per-row partials
#pragma unroll
        for (int s = 0; s < 8; s++) {
            int col = nc * NCHUNK + bcol + s * 8 + 2 * t4;
            float w2a = w2s[col], w2b = w2s[col + 1];
            p0 += leaky(acc[s][0]) * w2a + leaky(acc[s][1]) * w2b;
            p1 += leaky(acc[s][2]) * w2a + leaky(acc[s][3]) * w2b;
        }
    }

    // reduce over the 4 lanes of each quad (same row), then across warps via smem
    p0 += __shfl_xor_sync(0xffffffffu, p0, 1);
    p0 += __shfl_xor_sync(0xffffffffu, p0, 2);
    p1 += __shfl_xor_sync(0xffffffffu, p1, 1);
    p1 += __shfl_xor_sync(0xffffffffu, p1, 2);
    if (t4 == 0) {
        atomicAdd(&outs[arow + g],     p0);
        atomicAdd(&outs[arow + g + 8], p1);
    }
    __syncthreads();

    if (tid < TN)
        out[(size_t)(n0 + tid) * DNODES + d] = outs[tid];
}

extern "C" void kernel_launch(void* const* d_in, const int* in_sizes, int n_in,
                              void* d_out, int out_size) {
    (void)in_sizes; (void)n_in; (void)out_size;
    const float* x  = (const float*)d_in[0];
    const float* W0 = (const float*)d_in[1];
    const float* W1 = (const float*)d_in[2];
    const float* W2 = (const float*)d_in[3];
    float* out = (float*)d_out;

    cudaFuncSetAttribute(grandag_fused_kernel,
                         cudaFuncAttributeMaxDynamicSharedMemorySize, SMEM_BYTES);

    dim3 grid(NSAMP / TN, DNODES);   // x fastest -> same-d blocks co-resident (L2 W reuse)
    grandag_fused_kernel<<<grid, THREADS, SMEM_BYTES>>>(x, W0, W1, W2, out);
}

// round 4
// speedup vs baseline: 1.3459x; 1.3459x over previous
#include <cuda_runtime.h>
#include <cstdint>

#define DNODES 128
#define HID    512
#define NSAMP  2048
#define TM     64
#define THREADS 256
#define NTILES 40            // 8 (L0) + 32 (L1), KT=32, N-chunk=256

// smem float offsets
#define APH    0             // 64 slabs x 512 floats = 32768 floats (h1 packed)
#define APX    16384         // x packed: aliases APH slabs 32..47 (safe: see epilogue order)
#define BB0    32768
#define BROW   264           // floats per B row: 66 x 16B, 66 % 8 == 2 -> conflict-free
#define BTILE  (32*BROW)     // 8448
#define BB1    (BB0 + BTILE)
#define W2S    (BB1 + BTILE) // 49664
#define OUTS   (W2S + HID)   // 50176
#define SMEMF  (OUTS + TM)   // 50240
#define SMEMB  (SMEMF*4)     // 200960 bytes

// packed, tf32-rounded weights: [d][chunk(2)][k][j(256)]
__device__ float g_Wp0[(size_t)DNODES * 2 * DNODES * 256];
__device__ float g_Wp1[(size_t)DNODES * 2 * HID * 256];

__device__ __forceinline__ float to_tf32(float x) {
    asm("cvt.rna.tf32.f32 %0, %0;" : "+f"(x));
    return x;
}
__device__ __forceinline__ float leaky(float x) { return x > 0.0f ? x : 0.01f * x; }

__device__ __forceinline__ void mma_tf32(float c[4],
                                         uint32_t a0, uint32_t a1, uint32_t a2, uint32_t a3,
                                         uint32_t b0, uint32_t b1) {
    asm volatile(
        "mma.sync.aligned.m16n8k8.row.col.f32.tf32.tf32.f32 "
        "{%0,%1,%2,%3},{%4,%5,%6,%7},{%8,%9},{%0,%1,%2,%3};"
        : "+f"(c[0]), "+f"(c[1]), "+f"(c[2]), "+f"(c[3])
        : "r"(a0), "r"(a1), "r"(a2), "r"(a3), "r"(b0), "r"(b1));
}

__device__ __forceinline__ uint32_t smem_u32(const void* p) {
    uint32_t a;
    asm("{ .reg .u64 t; cvta.to.shared.u64 t, %1; cvt.u32.u64 %0, t; }" : "=r"(a) : "l"(p));
    return a;
}
#define CP_ASYNC16(sa, gp) \
    asm volatile("cp.async.cg.shared.global [%0], [%1], 16;" :: "r"((uint32_t)(sa)), "l"(gp) : "memory")
#define CP_COMMIT() asm volatile("cp.async.commit_group;" ::: "memory")
#define CP_WAIT1()  asm volatile("cp.async.wait_group 1;" ::: "memory")
#define CP_WAIT0()  asm volatile("cp.async.wait_group 0;" ::: "memory")

// ---------- prepass: pack + tf32-round weights into fragment order ----------
// Wp[d][c][k][j], j = wn*64 + sig*32 + g*4 + f  <-  W[d][k][c*256 + wn*64 + 32*sig + 8*f + g]
template <int K, int LOGK>
__global__ void pack_w(const float* __restrict__ W, float* __restrict__ Wp) {
    size_t idx = (size_t)blockIdx.x * THREADS + threadIdx.x;   // float4 id
    size_t total = (size_t)DNODES * 2 * K * 64;
    if (idx >= total) return;
    int j4 = (int)(idx & 63);
    size_t t2 = idx >> 6;
    int k = (int)(t2 & (K - 1));
    size_t t3 = t2 >> LOGK;
    int c = (int)(t3 & 1);
    int d = (int)(t3 >> 1);
    int j0 = j4 * 4;
    int wn = j0 >> 6, sig = (j0 >> 5) & 1, g = (j0 >> 2) & 7;
    int nb = c * 256 + wn * 64 + 32 * sig + g;
    const float* src = W + ((size_t)d * K + k) * HID;
    float4 v;
    v.x = to_tf32(src[nb]);
    v.y = to_tf32(src[nb + 8]);
    v.z = to_tf32(src[nb + 16]);
    v.w = to_tf32(src[nb + 24]);
    reinterpret_cast<float4*>(Wp)[idx] = v;
}

// ---------- main fused kernel ----------
extern __shared__ float sm[];

__global__ void __launch_bounds__(THREADS, 1)
grandag_mma_kernel(const float* __restrict__ x,
                   const float* __restrict__ W2,
                   float* __restrict__ out) {
    const int tid = threadIdx.x;
    const int warp = tid >> 5;
    const int lane = tid & 31;
    const int wm = warp & 1;      // 2 M-warps (32 rows each)
    const int wn = warp >> 1;     // 4 N-warps (64 cols each)
    const int g = lane >> 2;
    const int t4 = lane & 3;
    const int d = blockIdx.y;
    const int n0 = blockIdx.x * TM;
    const uint32_t sb = smem_u32(sm);

    // init outs + w2
    if (tid < TM) sm[OUTS + tid] = 0.0f;
    for (int i = tid; i < HID; i += THREADS)
        sm[W2S + i] = W2[(size_t)d * HID + i];

    // pack masked x -> APX fragment layout (16 k8-slabs)
    {
        const float* xb = x + (size_t)n0 * DNODES;
#pragma unroll
        for (int q = 0; q < 8; q++) {
            int idx4 = tid + q * THREADS;          // 0..2047
            int r = idx4 >> 5, i4 = idx4 & 31;
            float4 v = *reinterpret_cast<const float4*>(xb + (size_t)r * DNODES + i4 * 4);
            int dd = d - i4 * 4;
            if (dd == 0) v.x = 0.f; else if (dd == 1) v.y = 0.f;
            else if (dd == 2) v.z = 0.f; else if (dd == 3) v.w = 0.f;
            float vv[4] = { to_tf32(v.x), to_tf32(v.y), to_tf32(v.z), to_tf32(v.w) };
            int gp = r & 7, hf = (r >> 3) & 1, mf4 = r >> 4;
#pragma unroll
            for (int e = 0; e < 4; e++) {
                int i = i4 * 4 + e;
                int k8 = i >> 3, koff = i & 7;
                sm[APX + (k8 * 4 + mf4) * 128 + (gp * 4 + (koff & 3)) * 4 + (koff >> 2) * 2 + hf] = vv[e];
            }
        }
    }

    // tile source pointer (linear tile id 0..39)
    auto tsrc = [&](int t) -> const float* {
        if (t < 8) {
            int c = t >> 2, kt = t & 3;
            return g_Wp0 + (((size_t)d * 2 + c) * DNODES + kt * 32) * 256;
        }
        int u = t - 8;
        int c = u >> 4, kt = u & 15;
        return g_Wp1 + (((size_t)d * 2 + c) * HID + kt * 32) * 256;
    };
    auto stage = [&](int t) {
        const float* gsrc = tsrc(t);
        uint32_t dstb = sb + (uint32_t)((t & 1) ? BB1 : BB0) * 4;
#pragma unroll
        for (int q = 0; q < 8; q++) {
            int fid = tid + q * THREADS;           // 0..2047 (32 rows x 64 x16B)
            int row = fid >> 6, c16 = fid & 63;
            CP_ASYNC16(dstb + row * (BROW * 4) + c16 * 16, gsrc + (size_t)row * 256 + c16 * 4);
        }
    };

    stage(0);
    CP_COMMIT();

    float acc[2][8][4];
    float pr[4] = {0.f, 0.f, 0.f, 0.f};   // fused layer-2 partials per owned row

#pragma unroll 1
    for (int t = 0; t < NTILES; t++) {
        if (t + 1 < NTILES) { stage(t + 1); CP_COMMIT(); CP_WAIT1(); }
        else CP_WAIT0();
        __syncthreads();   // BAR#1: tile t visible everywhere

        bool first = (t < 8) ? ((t & 3) == 0) : (((t - 8) & 15) == 0);
        if (first) {
#pragma unroll
            for (int mf = 0; mf < 2; mf++)
#pragma unroll
                for (int s = 0; s < 8; s++)
#pragma unroll
                    for (int j = 0; j < 4; j++) acc[mf][s][j] = 0.f;
        }

        const int Abase = (t < 8) ? (APX + ((t & 3) * 4) * 512)
                                  : (APH + (((t - 8) & 15) * 4) * 512);
        const float* bb = sm + ((t & 1) ? BB1 : BB0);

#pragma unroll
        for (int step = 0; step < 4; step++) {
            const float4* Ap = reinterpret_cast<const float4*>(sm + Abase + step * 512)
                               + (wm * 2) * 32 + lane;
            float4 A0 = Ap[0];
            float4 A1 = Ap[32];
            const float* br = bb + (step * 8 + t4) * BROW + wn * 64 + g * 4;
            float4 b0lo = *reinterpret_cast<const float4*>(br);
            float4 b0hi = *reinterpret_cast<const float4*>(br + 32);
            float4 b1lo = *reinterpret_cast<const float4*>(br + 4 * BROW);
            float4 b1hi = *reinterpret_cast<const float4*>(br + 4 * BROW + 32);
            float b0s[8] = { b0lo.x, b0lo.y, b0lo.z, b0lo.w, b0hi.x, b0hi.y, b0hi.z, b0hi.w };
            float b1s[8] = { b1lo.x, b1lo.y, b1lo.z, b1lo.w, b1hi.x, b1hi.y, b1hi.z, b1hi.w };
            uint32_t a00 = __float_as_uint(A0.x), a01 = __float_as_uint(A0.y),
                     a02 = __float_as_uint(A0.z), a03 = __float_as_uint(A0.w);
            uint32_t a10 = __float_as_uint(A1.x), a11 = __float_as_uint(A1.y),
                     a12 = __float_as_uint(A1.z), a13 = __float_as_uint(A1.w);
#pragma unroll
            for (int s = 0; s < 8; s++) {
                uint32_t bb0 = __float_as_uint(b0s[s]);
                uint32_t bb1 = __float_as_uint(b1s[s]);
                mma_tf32(acc[0][s], a00, a01, a02, a03, bb0, bb1);
                mma_tf32(acc[1][s], a10, a11, a12, a13, bb0, bb1);
            }
        }

        __syncthreads();   // BAR#2: buffer (t&1) free for tile t+2

        // L0 chunk epilogue: leaky + round -> ApackH (chunk1 overwrites APX region: safe, X reads done)
        if (t == 3 || t == 7) {
            int c = t >> 2;
#pragma unroll
            for (int mf = 0; mf < 2; mf++) {
                int R = wm * 32 + mf * 16;
#pragma unroll
                for (int s = 0; s < 8; s++) {
                    int n = c * 256 + wn * 64 + 8 * s + 2 * t4;
#pragma unroll
                    for (int e = 0; e < 4; e++) {
                        int nn = n + (e & 1);
                        int r = R + g + (e >> 1) * 8;
                        float v = to_tf32(leaky(acc[mf][s][e]));
                        int k8 = nn >> 3, koff = nn & 7;
                        sm[APH + (k8 * 4 + (r >> 4)) * 128 +
                           ((r & 7) * 4 + (koff & 3)) * 4 + (koff >> 2) * 2 + ((r >> 3) & 1)] = v;
                    }
                }
            }
        }
        // L1 chunk epilogue: fused layer-2 dot (fp32)
        if (t == 23 || t == 39) {
            int c = (t - 8) >> 4;
#pragma unroll
            for (int mf = 0; mf < 2; mf++)
#pragma unroll
                for (int s = 0; s < 8; s++) {
                    int n = c * 256 + wn * 64 + 8 * s + 2 * t4;
                    float w2a = sm[W2S + n], w2b = sm[W2S + n + 1];
                    pr[mf * 2 + 0] += leaky(acc[mf][s][0]) * w2a + leaky(acc[mf][s][1]) * w2b;
                    pr[mf * 2 + 1] += leaky(acc[mf][s][2]) * w2a + leaky(acc[mf][s][3]) * w2b;
                }
        }
    }

    // reduce pr over quad (t4), then across wn warps via smem atomics
#pragma unroll
    for (int j = 0; j < 4; j++) {
        pr[j] += __shfl_xor_sync(0xffffffffu, pr[j], 1);
        pr[j] += __shfl_xor_sync(0xffffffffu, pr[j], 2);
    }
    if (t4 == 0) {
#pragma unroll
        for (int mf = 0; mf < 2; mf++) {
            int R = wm * 32 + mf * 16;
            atomicAdd(&sm[OUTS + R + g], pr[mf * 2 + 0]);
            atomicAdd(&sm[OUTS + R + g + 8], pr[mf * 2 + 1]);
        }
    }
    __syncthreads();
    if (tid < TM)
        out[(size_t)(n0 + tid) * DNODES + d] = sm[OUTS + tid];
}

extern "C" void kernel_launch(void* const* d_in, const int* in_sizes, int n_in,
                              void* d_out, int out_size) {
    (void)in_sizes; (void)n_in; (void)out_size;
    const float* x  = (const float*)d_in[0];
    const float* W0 = (const float*)d_in[1];
    const float* W1 = (const float*)d_in[2];
    const float* W2 = (const float*)d_in[3];
    float* out = (float*)d_out;

    float* wp0; cudaGetSymbolAddress((void**)&wp0, g_Wp0);
    float* wp1; cudaGetSymbolAddress((void**)&wp1, g_Wp1);

    // prepass: pack + round weights
    {
        size_t t0 = (size_t)DNODES * 2 * DNODES * 64;   // float4 count
        size_t t1 = (size_t)DNODES * 2 * HID * 64;
        pack_w<DNODES, 7><<<(unsigned)((t0 + THREADS - 1) / THREADS), THREADS>>>(W0, wp0);
        pack_w<HID, 9><<<(unsigned)((t1 + THREADS - 1) / THREADS), THREADS>>>(W1, wp1);
    }

    cudaFuncSetAttribute(grandag_mma_kernel,
                         cudaFuncAttributeMaxDynamicSharedMemorySize, SMEMB);
    dim3 grid(NSAMP / TM, DNODES);   // x fastest: same-d blocks co-resident (L2 Wp reuse)
    grandag_mma_kernel<<<grid, THREADS, SMEMB>>>(x, W2, out);
}

// round 5
// speedup vs baseline: 3.4437x; 2.5586x over previous
#include <cuda_runtime.h>
#include <cuda_fp16.h>
#include <cstdint>

#define DNODES 128
#define HID    512
#define NSAMP  2048
#define TM     64
#define THREADS 256
#define NTILES 40           // 8 (L0: K=128 x 2 chunks) + 32 (L1: K=512 x 2 chunks), KT=32

// smem byte offsets
#define APH_B   0                     // h1 packed: 32 ksteps x 4 mf x 512B = 64KB
#define APX_B   49152                 // x packed: 8 ksteps x 4 mf x 512B = 16KB (aliases APH ksteps 24..31)
#define BB_B    65536                 // 2 x 16KB B staging
#define BTILE_B 16384
#define W2_B    98304                 // 512 f32
#define OUTS_B  100352                // 64 f32
#define SMEMB   100608

// packed fp16 weights, fragment-major:
// [d][c(2)][kt][s(2)][q(16)][lane(32)] x 16B
__device__ __half g_Wp0[(size_t)DNODES * 2 * 4  * 2 * 16 * 32 * 8];
__device__ __half g_Wp1[(size_t)DNODES * 2 * 16 * 2 * 16 * 32 * 8];

__device__ __forceinline__ float leaky(float x) { return x > 0.0f ? x : 0.01f * x; }

__device__ __forceinline__ void mma_f16(float c[4], uint32_t a0, uint32_t a1,
                                        uint32_t a2, uint32_t a3,
                                        uint32_t b0, uint32_t b1) {
    asm volatile(
        "mma.sync.aligned.m16n8k16.row.col.f32.f16.f16.f32 "
        "{%0,%1,%2,%3},{%4,%5,%6,%7},{%8,%9},{%0,%1,%2,%3};"
        : "+f"(c[0]), "+f"(c[1]), "+f"(c[2]), "+f"(c[3])
        : "r"(a0), "r"(a1), "r"(a2), "r"(a3), "r"(b0), "r"(b1));
}
__device__ __forceinline__ uint32_t smem_u32(const void* p) {
    uint32_t a;
    asm("{ .reg .u64 t; cvta.to.shared.u64 t, %1; cvt.u32.u64 %0, t; }" : "=r"(a) : "l"(p));
    return a;
}
#define CP_ASYNC16(sa, gp) \
    asm volatile("cp.async.cg.shared.global [%0], [%1], 16;" :: "r"((uint32_t)(sa)), "l"(gp) : "memory")
#define CP_COMMIT() asm volatile("cp.async.commit_group;" ::: "memory")
#define CP_WAIT0()  asm volatile("cp.async.wait_group 0;" ::: "memory")

__device__ __forceinline__ uint32_t pack_h2(float lo, float hi) {
    __half2 h = __halves2half2(__float2half_rn(lo), __float2half_rn(hi));
    return *reinterpret_cast<uint32_t*>(&h);
}

// ---------- prepass: pack + fp16-round weights into fragment-major order ----------
// out uint4 idx: lane(5) | q(4) | s(1) | kt(LOGKT) | c(1) | d
// source: col = c*256 + (q>>2)*64 + (q&3)*16 + g + f*8
//         k   = kt*32 + s*16 + hb*8 + 2*t4 + lo   (j = f*4 + hb*2 + lo)
template <int KTOT, int LOGKT>
__global__ void pack_w(const float* __restrict__ W, __half* __restrict__ Wp) {
    size_t idx = (size_t)blockIdx.x * THREADS + threadIdx.x;
    size_t total = (size_t)DNODES * 2 * (KTOT / 32) * 2 * 16 * 32;
    if (idx >= total) return;
    int lane = (int)(idx & 31);
    int q    = (int)((idx >> 5) & 15);
    int s    = (int)((idx >> 9) & 1);
    int kt   = (int)((idx >> 10) & ((KTOT / 32) - 1));
    int c    = (int)((idx >> (10 + LOGKT)) & 1);
    int d    = (int)(idx >> (11 + LOGKT));
    int g = lane >> 2, t4 = lane & 3;
    int colb = c * 256 + (q >> 2) * 64 + (q & 3) * 16 + g;
    int kb = kt * 32 + s * 16 + 2 * t4;
    const float* src = W + (size_t)d * KTOT * HID;
    uint32_t r[4];
#pragma unroll
    for (int f = 0; f < 2; f++)
#pragma unroll
        for (int hb = 0; hb < 2; hb++) {
            int k = kb + hb * 8;
            int col = colb + f * 8;
            r[f * 2 + hb] = pack_h2(src[(size_t)k * HID + col],
                                    src[(size_t)(k + 1) * HID + col]);
        }
    reinterpret_cast<uint4*>(Wp)[idx] = make_uint4(r[0], r[1], r[2], r[3]);
}

// ---------- main fused kernel ----------
extern __shared__ char smc[];

__global__ void __launch_bounds__(THREADS, 2)
grandag_f16_kernel(const float* __restrict__ x,
                   const float* __restrict__ W2,
                   float* __restrict__ out) {
    const int tid = threadIdx.x;
    const int warp = tid >> 5;
    const int lane = tid & 31;
    const int wm = warp & 1;      // 2 M-warps (32 rows)
    const int wn = warp >> 1;     // 4 N-warps (64 cols)
    const int g = lane >> 2;
    const int t4 = lane & 3;
    const int d = blockIdx.y;
    const int n0 = blockIdx.x * TM;
    const uint32_t sb = smem_u32(smc);
    float* smf = reinterpret_cast<float*>(smc);

    if (tid < TM) smf[OUTS_B / 4 + tid] = 0.0f;
    for (int i = tid; i < HID; i += THREADS)
        smf[W2_B / 4 + i] = W2[(size_t)d * HID + i];

    // pack masked x -> APX fragment-major (K = warp, mf = i)
    {
        const float* xb = x + (size_t)n0 * DNODES;
        int K = warp;
        int k0 = K * 16 + 2 * t4;
#pragma unroll
        for (int mf = 0; mf < 4; mf++) {
            int r0 = mf * 16 + g, r1 = r0 + 8;
            float v[8];
            v[0] = xb[(size_t)r0 * DNODES + k0];     v[1] = xb[(size_t)r0 * DNODES + k0 + 1];
            v[2] = xb[(size_t)r1 * DNODES + k0];     v[3] = xb[(size_t)r1 * DNODES + k0 + 1];
            v[4] = xb[(size_t)r0 * DNODES + k0 + 8]; v[5] = xb[(size_t)r0 * DNODES + k0 + 9];
            v[6] = xb[(size_t)r1 * DNODES + k0 + 8]; v[7] = xb[(size_t)r1 * DNODES + k0 + 9];
            if (k0 == d)     { v[0] = 0.f; v[2] = 0.f; }
            if (k0 + 1 == d) { v[1] = 0.f; v[3] = 0.f; }
            if (k0 + 8 == d) { v[4] = 0.f; v[6] = 0.f; }
            if (k0 + 9 == d) { v[5] = 0.f; v[7] = 0.f; }
            uint4 u = make_uint4(pack_h2(v[0], v[1]), pack_h2(v[2], v[3]),
                                 pack_h2(v[4], v[5]), pack_h2(v[6], v[7]));
            *reinterpret_cast<uint4*>(smc + APX_B + (K * 4 + mf) * 512 + lane * 16) = u;
        }
    }

    auto tsrc = [&](int t) -> const __half* {
        if (t < 8) {
            int c = t >> 2, kt = t & 3;
            return g_Wp0 + ((((size_t)d * 2 + c) * 4 + kt) * 1024) * 8;
        }
        int u = t - 8;
        int c = u >> 4, kt = u & 15;
        return g_Wp1 + ((((size_t)d * 2 + c) * 16 + kt) * 1024) * 8;
    };
    auto stage = [&](int t) {
        const __half* gsrc = tsrc(t);
        uint32_t dstb = sb + BB_B + (uint32_t)(t & 1) * BTILE_B;
#pragma unroll
        for (int q = 0; q < 4; q++) {
            int fid = tid + q * THREADS;      // 0..1023 x 16B
            CP_ASYNC16(dstb + fid * 16, gsrc + (size_t)fid * 8);
        }
    };

    stage(0);
    CP_COMMIT();

    float acc[2][8][4];
    float pr[4] = {0.f, 0.f, 0.f, 0.f};

#pragma unroll 1
    for (int t = 0; t < NTILES; t++) {
        CP_WAIT0();
        __syncthreads();   // tile t visible; tile t-1 fully consumed everywhere
        if (t + 1 < NTILES) { stage(t + 1); CP_COMMIT(); }

        bool first = (t < 8) ? ((t & 3) == 0) : (((t - 8) & 15) == 0);
        if (first) {
#pragma unroll
            for (int mf = 0; mf < 2; mf++)
#pragma unroll
                for (int s = 0; s < 8; s++)
#pragma unroll
                    for (int j = 0; j < 4; j++) acc[mf][s][j] = 0.f;
        }

        const int abase = (t < 8) ? (APX_B + ((t & 3) * 2) * 4 * 512)
                                  : (APH_B + (((t - 8) & 15) * 2) * 4 * 512);
        const char* bb = smc + BB_B + (t & 1) * BTILE_B;

#pragma unroll
        for (int ks = 0; ks < 2; ks++) {
            uint4 a[2];
#pragma unroll
            for (int mf = 0; mf < 2; mf++)
                a[mf] = *reinterpret_cast<const uint4*>(
                    smc + abase + ((ks * 4) + wm * 2 + mf) * 512 + lane * 16);
#pragma unroll
            for (int p = 0; p < 4; p++) {
                uint4 b = *reinterpret_cast<const uint4*>(
                    bb + (((ks * 16) + wn * 4 + p) * 32 + lane) * 16);
                mma_f16(acc[0][2 * p],     a[0].x, a[0].y, a[0].z, a[0].w, b.x, b.y);
                mma_f16(acc[0][2 * p + 1], a[0].x, a[0].y, a[0].z, a[0].w, b.z, b.w);
                mma_f16(acc[1][2 * p],     a[1].x, a[1].y, a[1].z, a[1].w, b.x, b.y);
                mma_f16(acc[1][2 * p + 1], a[1].x, a[1].y, a[1].z, a[1].w, b.z, b.w);
            }
        }

        // L0 chunk epilogue: leaky -> fp16 -> APH (fragment-major, conflict-free STS.128)
        if (t == 3 || t == 7) {
            if (t == 7) __syncthreads();   // x reads done before overwriting aliased APX region
            int c = t >> 2;
#pragma unroll
            for (int mf = 0; mf < 2; mf++) {
#pragma unroll
                for (int p = 0; p < 4; p++) {
                    int K = c * 16 + wn * 4 + p;
                    int se = 2 * p, so = 2 * p + 1;
                    uint4 u = make_uint4(
                        pack_h2(leaky(acc[mf][se][0]), leaky(acc[mf][se][1])),
                        pack_h2(leaky(acc[mf][se][2]), leaky(acc[mf][se][3])),
                        pack_h2(leaky(acc[mf][so][0]), leaky(acc[mf][so][1])),
                        pack_h2(leaky(acc[mf][so][2]), leaky(acc[mf][so][3])));
                    *reinterpret_cast<uint4*>(
                        smc + APH_B + (K * 4 + wm * 2 + mf) * 512 + lane * 16) = u;
                }
            }
        }
        // L1 chunk epilogue: fused layer-2 dot (fp32)
        if (t == 23 || t == 39) {
            int c = (t - 8) >> 4;
#pragma unroll
            for (int mf = 0; mf < 2; mf++)
#pragma unroll
                for (int s = 0; s < 8; s++) {
                    int n = c * 256 + wn * 64 + 8 * s + 2 * t4;
                    float w2a = smf[W2_B / 4 + n], w2b = smf[W2_B / 4 + n + 1];
                    pr[mf * 2 + 0] += leaky(acc[mf][s][0]) * w2a + leaky(acc[mf][s][1]) * w2b;
                    pr[mf * 2 + 1] += leaky(acc[mf][s][2]) * w2a + leaky(acc[mf][s][3]) * w2b;
                }
        }
    }

#pragma unroll
    for (int j = 0; j < 4; j++) {
        pr[j] += __shfl_xor_sync(0xffffffffu, pr[j], 1);
        pr[j] += __shfl_xor_sync(0xffffffffu, pr[j], 2);
    }
    if (t4 == 0) {
#pragma unroll
        for (int mf = 0; mf < 2; mf++) {
            int R = wm * 32 + mf * 16;
            atomicAdd(&smf[OUTS_B / 4 + R + g], pr[mf * 2 + 0]);
            atomicAdd(&smf[OUTS_B / 4 + R + g + 8], pr[mf * 2 + 1]);
        }
    }
    __syncthreads();
    if (tid < TM)
        out[(size_t)(n0 + tid) * DNODES + d] = smf[OUTS_B / 4 + tid];
}

extern "C" void kernel_launch(void* const* d_in, const int* in_sizes, int n_in,
                              void* d_out, int out_size) {
    (void)in_sizes; (void)n_in; (void)out_size;
    const float* x  = (const float*)d_in[0];
    const float* W0 = (const float*)d_in[1];
    const float* W1 = (const float*)d_in[2];
    const float* W2 = (const float*)d_in[3];
    float* out = (float*)d_out;

    __half* wp0; cudaGetSymbolAddress((void**)&wp0, g_Wp0);
    __half* wp1; cudaGetSymbolAddress((void**)&wp1, g_Wp1);

    {
        size_t t0 = (size_t)DNODES * 2 * 4 * 2 * 16 * 32;    // uint4 count L0
        size_t t1 = (size_t)DNODES * 2 * 16 * 2 * 16 * 32;   // uint4 count L1
        pack_w<DNODES, 2><<<(unsigned)((t0 + THREADS - 1) / THREADS), THREADS>>>(W0, wp0);
        pack_w<HID, 4><<<(unsigned)((t1 + THREADS - 1) / THREADS), THREADS>>>(W1, wp1);
    }

    cudaFuncSetAttribute(grandag_f16_kernel,
                         cudaFuncAttributeMaxDynamicSharedMemorySize, SMEMB);
    dim3 grid(NSAMP / TM, DNODES);   // x fastest: same-d blocks co-resident (L2 weight reuse)
    grandag_f16_kernel<<<grid, THREADS, SMEMB>>>(x, W2, out);
}